// round 1
// baseline (speedup 1.0000x reference)
#include <cuda_runtime.h>
#include <math.h>

#define N_NODES 2048
#define BATCH   32
#define HIDDEN  64
#define DIM_IN  2
#define C_IN    66                 // DIM_IN + HIDDEN
#define BC      (BATCH * C_IN)     // 2112
#define IN3     (3 * C_IN)         // 198
#define GATE_OUT 128
#define UPD_OUT  64

// ---------------- device scratch (static: no allocations allowed) ----------
__device__ float g_S [N_NODES * N_NODES];   // supports, 16.8 MB
__device__ float g_X0[N_NODES * BC];        // T0 = cat(x,state)  [N, B*C]
__device__ float g_X1[N_NODES * BC];        // T1 = A @ T0
__device__ float g_X2[N_NODES * BC];        // T2 = 2 A T1 - T0
__device__ float g_C0[N_NODES * BC];        // candidate T0 = cat(x, z*state)
__device__ float g_r [BATCH * N_NODES * HIDDEN];

// ---------------- K1: supports = softmax(relu(E E^T), axis=1) --------------
__global__ void supports_kernel(const float* __restrict__ E) {
    int n = blockIdx.x;
    int t = threadIdx.x;                      // 256 threads, 8 cols each
    float e[10];
#pragma unroll
    for (int c = 0; c < 10; c++) e[c] = E[n * 10 + c];

    float vals[8];
    float vmax = 0.0f;                        // relu -> all >= 0
#pragma unroll
    for (int j = 0; j < 8; j++) {
        int m = j * 256 + t;
        float s = 0.0f;
#pragma unroll
        for (int c = 0; c < 10; c++) s = fmaf(e[c], E[m * 10 + c], s);
        s = fmaxf(s, 0.0f);
        vals[j] = s;
        vmax = fmaxf(vmax, s);
    }
    __shared__ float red[256];
    red[t] = vmax; __syncthreads();
    for (int s = 128; s > 0; s >>= 1) {
        if (t < s) red[t] = fmaxf(red[t], red[t + s]);
        __syncthreads();
    }
    vmax = red[0]; __syncthreads();

    float lsum = 0.0f;
#pragma unroll
    for (int j = 0; j < 8; j++) { vals[j] = expf(vals[j] - vmax); lsum += vals[j]; }
    red[t] = lsum; __syncthreads();
    for (int s = 128; s > 0; s >>= 1) {
        if (t < s) red[t] += red[t + s];
        __syncthreads();
    }
    float inv = 1.0f / red[0];
#pragma unroll
    for (int j = 0; j < 8; j++) g_S[n * N_NODES + j * 256 + t] = vals[j] * inv;
}

// ---------------- K2: pack X0[n][b*66+c] = cat(x, state) -------------------
__global__ void pack_kernel(const float* __restrict__ x, const float* __restrict__ st) {
    int n = blockIdx.x;
    for (int i = threadIdx.x; i < BC; i += blockDim.x) {
        int b = i / C_IN, c = i - b * C_IN;
        float v = (c < 2) ? x[(b * N_NODES + n) * 2 + c]
                          : st[(b * N_NODES + n) * 64 + (c - 2)];
        g_X0[n * BC + i] = v;
    }
}

// ---------------- SGEMM: C = A @ B  (MODE 1: C = 2*acc - Aux) --------------
// A: [2048,2048] row-major, B/C/Aux: [2048,2112] row-major.
template <int MODE>
__global__ void __launch_bounds__(256)
gemm_kernel(const float* __restrict__ A, const float* __restrict__ B,
            const float* __restrict__ Aux, float* __restrict__ C) {
    const int Nc = BC, K = N_NODES;
    const int BM = 128, BN = 64, BK = 16;
    __shared__ float As[BK][BM];   // transposed A tile
    __shared__ float Bs[BK][BN];

    int bm = blockIdx.y, bn = blockIdx.x;
    int tid = threadIdx.x;
    int tr = tid >> 4;             // 0..15 (8 rows each)
    int tc = tid & 15;             // 0..15 (4 cols each)

    float acc[8][4];
#pragma unroll
    for (int m = 0; m < 8; m++)
#pragma unroll
        for (int nn = 0; nn < 4; nn++) acc[m][nn] = 0.0f;

    const float* Ablk = A + bm * BM * K;
    const float* Bblk = B + bn * BN;

    for (int k0 = 0; k0 < K; k0 += BK) {
        // load A tile: 128x16 = 512 float4, 2 per thread, store transposed
#pragma unroll
        for (int i = 0; i < 2; i++) {
            int p = tid * 2 + i;
            int row = p >> 2;
            int kq  = (p & 3) << 2;
            float4 v = *(const float4*)(Ablk + row * K + k0 + kq);
            As[kq + 0][row] = v.x; As[kq + 1][row] = v.y;
            As[kq + 2][row] = v.z; As[kq + 3][row] = v.w;
        }
        // load B tile: 16x64 = 256 float4, 1 per thread
        {
            int krow = tid >> 4;
            int c4   = (tid & 15) << 2;
            *(float4*)&Bs[krow][c4] = *(const float4*)(Bblk + (k0 + krow) * Nc + c4);
        }
        __syncthreads();

#pragma unroll
        for (int kk = 0; kk < BK; kk++) {
            float4 a0 = *(float4*)&As[kk][tr * 8];
            float4 a1 = *(float4*)&As[kk][tr * 8 + 4];
            float4 b0 = *(float4*)&Bs[kk][tc * 4];
            float av[8] = {a0.x, a0.y, a0.z, a0.w, a1.x, a1.y, a1.z, a1.w};
            float bv[4] = {b0.x, b0.y, b0.z, b0.w};
#pragma unroll
            for (int m = 0; m < 8; m++)
#pragma unroll
                for (int nn = 0; nn < 4; nn++)
                    acc[m][nn] = fmaf(av[m], bv[nn], acc[m][nn]);
        }
        __syncthreads();
    }

#pragma unroll
    for (int m = 0; m < 8; m++) {
        int row = bm * BM + tr * 8 + m;
        int col = bn * BN + tc * 4;
        float4 v = make_float4(acc[m][0], acc[m][1], acc[m][2], acc[m][3]);
        if (MODE == 1) {
            float4 a4 = *(const float4*)(Aux + row * Nc + col);
            v.x = 2.0f * v.x - a4.x; v.y = 2.0f * v.y - a4.y;
            v.z = 2.0f * v.z - a4.z; v.w = 2.0f * v.w - a4.w;
        }
        *(float4*)(C + row * Nc + col) = v;
    }
}

// ---------------- K4: gate projection + sigmoid + candidate pack -----------
// 16 rows (b,n) per block, 128 threads = 128 gate outputs.
__global__ void __launch_bounds__(128)
gate_kernel(const float* __restrict__ x, const float* __restrict__ st,
            const float* __restrict__ Wg, const float* __restrict__ bg) {
    __shared__ float in_s[16][IN3];
    int row0 = blockIdx.x * 16;
    int t = threadIdx.x;

    for (int idx = t; idx < 16 * IN3; idx += 128) {
        int rr = idx / IN3, i = idx - rr * IN3;
        int row = row0 + rr;
        int b = row >> 11, n = row & 2047;
        int k = i / C_IN, c = i - k * C_IN;
        const float* src = (k == 0) ? g_X0 : (k == 1) ? g_X1 : g_X2;
        in_s[rr][i] = src[n * BC + b * C_IN + c];
    }
    __syncthreads();

    int o = t;
    float acc[16];
#pragma unroll
    for (int rr = 0; rr < 16; rr++) acc[rr] = 0.0f;
    for (int i = 0; i < IN3; i++) {
        float w = Wg[i * GATE_OUT + o];
#pragma unroll
        for (int rr = 0; rr < 16; rr++) acc[rr] = fmaf(in_s[rr][i], w, acc[rr]);
    }
    float bias = bg[o];
#pragma unroll
    for (int rr = 0; rr < 16; rr++) {
        int row = row0 + rr;
        int b = row >> 11, n = row & 2047;
        float v = 1.0f / (1.0f + expf(-(acc[rr] + bias)));
        if (o < 64) {
            float sv = st[row * 64 + o];
            g_C0[n * BC + b * C_IN + 2 + o] = v * sv;       // z * state
            if (o < 2) g_C0[n * BC + b * C_IN + o] = x[row * 2 + o];
        } else {
            g_r[row * 64 + (o - 64)] = v;                    // r gate
        }
    }
}

// ---------------- K5: update projection + tanh + GRU blend -----------------
// 16 rows per block, 128 threads: o = t&63, half hh = t>>6 handles 8 rows.
__global__ void __launch_bounds__(128)
update_kernel(const float* __restrict__ st, const float* __restrict__ Wu,
              const float* __restrict__ bu, float* __restrict__ out) {
    __shared__ float in_s[16][IN3];
    int row0 = blockIdx.x * 16;
    int t = threadIdx.x;

    for (int idx = t; idx < 16 * IN3; idx += 128) {
        int rr = idx / IN3, i = idx - rr * IN3;
        int row = row0 + rr;
        int b = row >> 11, n = row & 2047;
        int k = i / C_IN, c = i - k * C_IN;
        const float* src = (k == 0) ? g_C0 : (k == 1) ? g_X0 : g_X1; // C1->X0, C2->X1
        in_s[rr][i] = src[n * BC + b * C_IN + c];
    }
    __syncthreads();

    int o = t & 63, hh = t >> 6;
    float acc[8];
#pragma unroll
    for (int rr = 0; rr < 8; rr++) acc[rr] = 0.0f;
    for (int i = 0; i < IN3; i++) {
        float w = Wu[i * UPD_OUT + o];
#pragma unroll
        for (int rr = 0; rr < 8; rr++) acc[rr] = fmaf(in_s[hh * 8 + rr][i], w, acc[rr]);
    }
    float bias = bu[o];
#pragma unroll
    for (int rr = 0; rr < 8; rr++) {
        int row = row0 + hh * 8 + rr;
        float hc = tanhf(acc[rr] + bias);
        float rv = g_r[row * 64 + o];
        float sv = st[row * 64 + o];
        out[row * 64 + o] = rv * sv + (1.0f - rv) * hc;
    }
}

// ---------------- launch ----------------------------------------------------
extern "C" void kernel_launch(void* const* d_in, const int* in_sizes, int n_in,
                              void* d_out, int out_size) {
    const float* x  = (const float*)d_in[0];
    const float* st = (const float*)d_in[1];
    const float* E  = (const float*)d_in[2];
    const float* Wg = (const float*)d_in[3];
    const float* bg = (const float*)d_in[4];
    const float* Wu = (const float*)d_in[5];
    const float* bu = (const float*)d_in[6];
    float* out = (float*)d_out;

    float *pS, *pX0, *pX1, *pX2, *pC0;
    cudaGetSymbolAddress((void**)&pS,  g_S);
    cudaGetSymbolAddress((void**)&pX0, g_X0);
    cudaGetSymbolAddress((void**)&pX1, g_X1);
    cudaGetSymbolAddress((void**)&pX2, g_X2);
    cudaGetSymbolAddress((void**)&pC0, g_C0);

    dim3 gg(BC / 64, N_NODES / 128);   // (33, 16)

    supports_kernel<<<N_NODES, 256>>>(E);
    pack_kernel<<<N_NODES, 256>>>(x, st);

    // gate gconv: X1 = A X0 ; X2 = 2 A X1 - X0
    gemm_kernel<0><<<gg, 256>>>(pS, pX0, nullptr, pX1);
    gemm_kernel<1><<<gg, 256>>>(pS, pX1, pX0, pX2);

    gate_kernel<<<(BATCH * N_NODES) / 16, 128>>>(x, st, Wg, bg);

    // update gconv: C1 = A C0 (->X0) ; C2 = 2 A C1 - C0 (->X1)
    gemm_kernel<0><<<gg, 256>>>(pS, pC0, nullptr, pX0);
    gemm_kernel<1><<<gg, 256>>>(pS, pX0, pC0, pX1);

    update_kernel<<<(BATCH * N_NODES) / 16, 128>>>(st, Wu, bu, out);
}

// round 3
// speedup vs baseline: 1.0135x; 1.0135x over previous
#include <cuda_runtime.h>
#include <math.h>

#define N_NODES 2048
#define BATCH   32
#define HIDDEN  64
#define DIM_IN  2
#define C_IN    66                 // DIM_IN + HIDDEN
#define BC      (BATCH * C_IN)     // 2112
#define IN3     (3 * C_IN)         // 198
#define GATE_OUT 128
#define UPD_OUT  64

// ---------------- device scratch (static: no allocations allowed) ----------
__device__ float g_S [N_NODES * N_NODES];   // supports, 16.8 MB
__device__ float g_X0[N_NODES * BC];        // T0 = cat(x,state)  [N, B*C]
__device__ float g_X1[N_NODES * BC];        // T1 = A @ T0
__device__ float g_X2[N_NODES * BC];        // T2 = 2 A T1 - T0
__device__ float g_C0[N_NODES * BC];        // candidate T0 = cat(x, z*state)
__device__ float g_r [BATCH * N_NODES * HIDDEN];

// ---------------- f32x2 helpers (sm_103a packed fp32) ----------------------
__device__ __forceinline__ unsigned long long pack_dup(float b) {
    unsigned long long r;
    asm("mov.b64 %0, {%1, %1};" : "=l"(r) : "f"(b));
    return r;
}
__device__ __forceinline__ void ffma2(unsigned long long& d,
                                      unsigned long long a,
                                      unsigned long long b) {
    asm("fma.rn.f32x2 %0, %1, %2, %0;" : "+l"(d) : "l"(a), "l"(b));
}

// ---------------- K1: supports = softmax(relu(E E^T), axis=1) --------------
__global__ void supports_kernel(const float* __restrict__ E) {
    int n = blockIdx.x;
    int t = threadIdx.x;                      // 256 threads, 8 cols each
    float e[10];
#pragma unroll
    for (int c = 0; c < 10; c++) e[c] = E[n * 10 + c];

    float vals[8];
    float vmax = 0.0f;                        // relu -> all >= 0
#pragma unroll
    for (int j = 0; j < 8; j++) {
        int m = j * 256 + t;
        float s = 0.0f;
#pragma unroll
        for (int c = 0; c < 10; c++) s = fmaf(e[c], E[m * 10 + c], s);
        s = fmaxf(s, 0.0f);
        vals[j] = s;
        vmax = fmaxf(vmax, s);
    }
    __shared__ float red[256];
    red[t] = vmax; __syncthreads();
    for (int s = 128; s > 0; s >>= 1) {
        if (t < s) red[t] = fmaxf(red[t], red[t + s]);
        __syncthreads();
    }
    vmax = red[0]; __syncthreads();

    float lsum = 0.0f;
#pragma unroll
    for (int j = 0; j < 8; j++) { vals[j] = expf(vals[j] - vmax); lsum += vals[j]; }
    red[t] = lsum; __syncthreads();
    for (int s = 128; s > 0; s >>= 1) {
        if (t < s) red[t] += red[t + s];
        __syncthreads();
    }
    float inv = 1.0f / red[0];
#pragma unroll
    for (int j = 0; j < 8; j++) g_S[n * N_NODES + j * 256 + t] = vals[j] * inv;
}

// ---------------- K2: pack X0[n][b*66+c] = cat(x, state) -------------------
__global__ void pack_kernel(const float* __restrict__ x, const float* __restrict__ st) {
    int n = blockIdx.x;
    for (int i = threadIdx.x; i < BC; i += blockDim.x) {
        int b = i / C_IN, c = i - b * C_IN;
        float v = (c < 2) ? x[(b * N_NODES + n) * 2 + c]
                          : st[(b * N_NODES + n) * 64 + (c - 2)];
        g_X0[n * BC + i] = v;
    }
}

// ---------------- SGEMM (FFMA2): C = A @ B  (MODE 1: C = 2*acc - Aux) ------
// A: [2048,2048] row-major, B/C/Aux: [2048,2112] row-major.
// 128x64x16 tile, 128 threads, 8x8 per thread, accumulators paired along M
// as f32x2; double-buffered smem, one sync per k-tile.
template <int MODE>
__global__ void __launch_bounds__(128)
gemm_kernel(const float* __restrict__ A, const float* __restrict__ B,
            const float* __restrict__ Aux, float* __restrict__ C) {
    const int Nc = BC, K = N_NODES;
    const int BM = 128, BN = 64, BK = 16;
    __shared__ float As[2][BK][BM];   // transposed A tile
    __shared__ float Bs[2][BK][BN];

    int bm = blockIdx.y, bn = blockIdx.x;
    int tid = threadIdx.x;
    int tr = tid >> 3;             // 0..15 : rows tr*8 .. tr*8+7
    int tc = tid & 7;              // 0..7  : cols tc*8 .. tc*8+7

    const float* Ablk = A + bm * BM * K;
    const float* Bblk = B + bn * BN;

    unsigned long long acc[4][8];  // [m-pair][n], each = (row 2p, row 2p+1)
#pragma unroll
    for (int p = 0; p < 4; p++)
#pragma unroll
        for (int n = 0; n < 8; n++) acc[p][n] = 0ULL;

    float4 aReg[4];
    float4 bReg[2];

#define LOAD_TILE(k0)                                                    \
    {                                                                    \
        _Pragma("unroll")                                                \
        for (int i = 0; i < 4; i++) {                                    \
            int idx = i * 128 + tid;                                     \
            int row = idx >> 2;                                          \
            int kq  = (idx & 3) << 2;                                    \
            aReg[i] = *(const float4*)(Ablk + row * K + (k0) + kq);      \
        }                                                                \
        _Pragma("unroll")                                                \
        for (int i = 0; i < 2; i++) {                                    \
            int idx = i * 128 + tid;                                     \
            int kr  = idx >> 4;                                          \
            int c4  = (idx & 15) << 2;                                   \
            bReg[i] = *(const float4*)(Bblk + ((k0) + kr) * Nc + c4);    \
        }                                                                \
    }

#define STORE_TILE(bufi)                                                 \
    {                                                                    \
        _Pragma("unroll")                                                \
        for (int i = 0; i < 4; i++) {                                    \
            int idx = i * 128 + tid;                                     \
            int row = idx >> 2;                                          \
            int kq  = (idx & 3) << 2;                                    \
            As[bufi][kq + 0][row] = aReg[i].x;                           \
            As[bufi][kq + 1][row] = aReg[i].y;                           \
            As[bufi][kq + 2][row] = aReg[i].z;                           \
            As[bufi][kq + 3][row] = aReg[i].w;                           \
        }                                                                \
        _Pragma("unroll")                                                \
        for (int i = 0; i < 2; i++) {                                    \
            int idx = i * 128 + tid;                                     \
            int kr  = idx >> 4;                                          \
            int c4  = (idx & 15) << 2;                                   \
            *(float4*)&Bs[bufi][kr][c4] = bReg[i];                       \
        }                                                                \
    }

    LOAD_TILE(0);
    STORE_TILE(0);
    __syncthreads();

    int buf = 0;
    for (int k0 = 0; k0 < K; k0 += BK) {
        bool more = (k0 + BK) < K;
        if (more) LOAD_TILE(k0 + BK);

#pragma unroll
        for (int kk = 0; kk < BK; kk++) {
            ulonglong2 aP0 = *(ulonglong2*)&As[buf][kk][tr * 8];
            ulonglong2 aP1 = *(ulonglong2*)&As[buf][kk][tr * 8 + 4];
            float4 b0 = *(float4*)&Bs[buf][kk][tc * 8];
            float4 b1 = *(float4*)&Bs[buf][kk][tc * 8 + 4];
            unsigned long long ap[4] = {aP0.x, aP0.y, aP1.x, aP1.y};
            unsigned long long bd[8];
            bd[0] = pack_dup(b0.x); bd[1] = pack_dup(b0.y);
            bd[2] = pack_dup(b0.z); bd[3] = pack_dup(b0.w);
            bd[4] = pack_dup(b1.x); bd[5] = pack_dup(b1.y);
            bd[6] = pack_dup(b1.z); bd[7] = pack_dup(b1.w);
#pragma unroll
            for (int p = 0; p < 4; p++)
#pragma unroll
                for (int n = 0; n < 8; n++)
                    ffma2(acc[p][n], ap[p], bd[n]);
        }

        if (more) STORE_TILE(buf ^ 1);
        __syncthreads();
        buf ^= 1;
    }

    // epilogue: unpack pairs, optional Chebyshev combine, vectorized store
#pragma unroll
    for (int p = 0; p < 4; p++) {
#pragma unroll
        for (int h = 0; h < 2; h++) {
            int row = bm * BM + tr * 8 + 2 * p + h;
            float o[8];
#pragma unroll
            for (int n = 0; n < 8; n++) {
                float2 f = *(float2*)&acc[p][n];
                o[n] = h ? f.y : f.x;
            }
            int col = bn * BN + tc * 8;
            float4 v0 = make_float4(o[0], o[1], o[2], o[3]);
            float4 v1 = make_float4(o[4], o[5], o[6], o[7]);
            if (MODE == 1) {
                float4 x0 = *(const float4*)(Aux + row * Nc + col);
                float4 x1 = *(const float4*)(Aux + row * Nc + col + 4);
                v0.x = 2.f * v0.x - x0.x; v0.y = 2.f * v0.y - x0.y;
                v0.z = 2.f * v0.z - x0.z; v0.w = 2.f * v0.w - x0.w;
                v1.x = 2.f * v1.x - x1.x; v1.y = 2.f * v1.y - x1.y;
                v1.z = 2.f * v1.z - x1.z; v1.w = 2.f * v1.w - x1.w;
            }
            *(float4*)(C + row * Nc + col)     = v0;
            *(float4*)(C + row * Nc + col + 4) = v1;
        }
    }
#undef LOAD_TILE
#undef STORE_TILE
}

// ---------------- K4: gate projection + sigmoid + candidate pack -----------
// 16 rows (b,n) per block, 128 threads = 128 gate outputs.
__global__ void __launch_bounds__(128)
gate_kernel(const float* __restrict__ x, const float* __restrict__ st,
            const float* __restrict__ Wg, const float* __restrict__ bg) {
    __shared__ float in_s[16][IN3];
    int row0 = blockIdx.x * 16;
    int t = threadIdx.x;

    for (int idx = t; idx < 16 * IN3; idx += 128) {
        int rr = idx / IN3, i = idx - rr * IN3;
        int row = row0 + rr;
        int b = row >> 11, n = row & 2047;
        int k = i / C_IN, c = i - k * C_IN;
        const float* src = (k == 0) ? g_X0 : (k == 1) ? g_X1 : g_X2;
        in_s[rr][i] = src[n * BC + b * C_IN + c];
    }
    __syncthreads();

    int o = t;
    float acc[16];
#pragma unroll
    for (int rr = 0; rr < 16; rr++) acc[rr] = 0.0f;
    for (int i = 0; i < IN3; i++) {
        float w = Wg[i * GATE_OUT + o];
#pragma unroll
        for (int rr = 0; rr < 16; rr++) acc[rr] = fmaf(in_s[rr][i], w, acc[rr]);
    }
    float bias = bg[o];
#pragma unroll
    for (int rr = 0; rr < 16; rr++) {
        int row = row0 + rr;
        int b = row >> 11, n = row & 2047;
        float v = 1.0f / (1.0f + expf(-(acc[rr] + bias)));
        if (o < 64) {
            float sv = st[row * 64 + o];
            g_C0[n * BC + b * C_IN + 2 + o] = v * sv;       // z * state
            if (o < 2) g_C0[n * BC + b * C_IN + o] = x[row * 2 + o];
        } else {
            g_r[row * 64 + (o - 64)] = v;                    // r gate
        }
    }
}

// ---------------- K5: update projection + tanh + GRU blend -----------------
// 16 rows per block, 128 threads: o = t&63, half hh = t>>6 handles 8 rows.
__global__ void __launch_bounds__(128)
update_kernel(const float* __restrict__ st, const float* __restrict__ Wu,
              const float* __restrict__ bu, float* __restrict__ out) {
    __shared__ float in_s[16][IN3];
    int row0 = blockIdx.x * 16;
    int t = threadIdx.x;

    for (int idx = t; idx < 16 * IN3; idx += 128) {
        int rr = idx / IN3, i = idx - rr * IN3;
        int row = row0 + rr;
        int b = row >> 11, n = row & 2047;
        int k = i / C_IN, c = i - k * C_IN;
        const float* src = (k == 0) ? g_C0 : (k == 1) ? g_X0 : g_X1; // C1->X0, C2->X1
        in_s[rr][i] = src[n * BC + b * C_IN + c];
    }
    __syncthreads();

    int o = t & 63, hh = t >> 6;
    float acc[8];
#pragma unroll
    for (int rr = 0; rr < 8; rr++) acc[rr] = 0.0f;
    for (int i = 0; i < IN3; i++) {
        float w = Wu[i * UPD_OUT + o];
#pragma unroll
        for (int rr = 0; rr < 8; rr++) acc[rr] = fmaf(in_s[hh * 8 + rr][i], w, acc[rr]);
    }
    float bias = bu[o];
#pragma unroll
    for (int rr = 0; rr < 8; rr++) {
        int row = row0 + hh * 8 + rr;
        float hc = tanhf(acc[rr] + bias);
        float rv = g_r[row * 64 + o];
        float sv = st[row * 64 + o];
        out[row * 64 + o] = rv * sv + (1.0f - rv) * hc;
    }
}

// ---------------- launch ----------------------------------------------------
extern "C" void kernel_launch(void* const* d_in, const int* in_sizes, int n_in,
                              void* d_out, int out_size) {
    const float* x  = (const float*)d_in[0];
    const float* st = (const float*)d_in[1];
    const float* E  = (const float*)d_in[2];
    const float* Wg = (const float*)d_in[3];
    const float* bg = (const float*)d_in[4];
    const float* Wu = (const float*)d_in[5];
    const float* bu = (const float*)d_in[6];
    float* out = (float*)d_out;

    float *pS, *pX0, *pX1, *pX2, *pC0;
    cudaGetSymbolAddress((void**)&pS,  g_S);
    cudaGetSymbolAddress((void**)&pX0, g_X0);
    cudaGetSymbolAddress((void**)&pX1, g_X1);
    cudaGetSymbolAddress((void**)&pX2, g_X2);
    cudaGetSymbolAddress((void**)&pC0, g_C0);

    dim3 gg(BC / 64, N_NODES / 128);   // (33, 16)

    supports_kernel<<<N_NODES, 256>>>(E);
    pack_kernel<<<N_NODES, 256>>>(x, st);

    // gate gconv: X1 = A X0 ; X2 = 2 A X1 - X0
    gemm_kernel<0><<<gg, 128>>>(pS, pX0, nullptr, pX1);
    gemm_kernel<1><<<gg, 128>>>(pS, pX1, pX0, pX2);

    gate_kernel<<<(BATCH * N_NODES) / 16, 128>>>(x, st, Wg, bg);

    // update gconv: C1 = A C0 (->X0) ; C2 = 2 A C1 - C0 (->X1)
    gemm_kernel<0><<<gg, 128>>>(pS, pC0, nullptr, pX0);
    gemm_kernel<1><<<gg, 128>>>(pS, pX0, pC0, pX1);

    update_kernel<<<(BATCH * N_NODES) / 16, 128>>>(st, Wu, bu, out);
}

// round 5
// speedup vs baseline: 1.7224x; 1.6995x over previous
#include <cuda_runtime.h>
#include <cuda_bf16.h>
#include <math.h>
#include <stdint.h>

#define N_NODES 2048
#define BATCH   32
#define HIDDEN  64
#define C_IN    66                 // DIM_IN + HIDDEN
#define BC      2112               // BATCH * C_IN
#define NPAD    2176               // BC padded to multiple of 128
#define IN3     198                // 3 * C_IN
#define GATE_OUT 128
#define UPD_OUT  64

// ---------------- device scratch (static: no allocations allowed) ----------
__device__ __nv_bfloat16 g_Ahi[N_NODES * N_NODES];
__device__ __nv_bfloat16 g_Alo[N_NODES * N_NODES];
__device__ __nv_bfloat16 g_X0Thi[NPAD * N_NODES];
__device__ __nv_bfloat16 g_X0Tlo[NPAD * N_NODES];
__device__ __nv_bfloat16 g_X1Thi[NPAD * N_NODES];
__device__ __nv_bfloat16 g_X1Tlo[NPAD * N_NODES];
__device__ __nv_bfloat16 g_C0Thi[NPAD * N_NODES];
__device__ __nv_bfloat16 g_C0Tlo[NPAD * N_NODES];
__device__ __nv_bfloat16 g_C1Thi[NPAD * N_NODES];
__device__ __nv_bfloat16 g_C1Tlo[NPAD * N_NODES];
__device__ float g_X0[N_NODES * BC];
__device__ float g_X1[N_NODES * BC];
__device__ float g_X2[N_NODES * BC];
__device__ float g_C0[N_NODES * BC];
__device__ float g_C1[N_NODES * BC];
__device__ float g_C2[N_NODES * BC];
__device__ float g_r [BATCH * N_NODES * HIDDEN];

__device__ __forceinline__ uint32_t smem_to_u32(const void* p) {
    uint32_t a;
    asm("{ .reg .u64 t; cvta.to.shared.u64 t, %1; cvt.u32.u64 %0, t; }" : "=r"(a) : "l"(p));
    return a;
}
__device__ __forceinline__ void split_bf16(float v, __nv_bfloat16& hi, __nv_bfloat16& lo) {
    hi = __float2bfloat16(v);
    lo = __float2bfloat16(v - __bfloat162float(hi));
}
__device__ __forceinline__ void mma_bf16(float* c, const uint32_t* a, const uint32_t* b) {
    asm volatile(
        "mma.sync.aligned.m16n8k16.row.col.f32.bf16.bf16.f32 "
        "{%0,%1,%2,%3}, {%4,%5,%6,%7}, {%8,%9}, {%0,%1,%2,%3};"
        : "+f"(c[0]), "+f"(c[1]), "+f"(c[2]), "+f"(c[3])
        : "r"(a[0]), "r"(a[1]), "r"(a[2]), "r"(a[3]), "r"(b[0]), "r"(b[1]));
}
__device__ __forceinline__ void ldsm4(uint32_t* r, uint32_t addr) {
    asm volatile("ldmatrix.sync.aligned.m8n8.x4.shared.b16 {%0,%1,%2,%3}, [%4];"
                 : "=r"(r[0]), "=r"(r[1]), "=r"(r[2]), "=r"(r[3]) : "r"(addr));
}
__device__ __forceinline__ void cp16(uint32_t daddr, const void* g) {
    asm volatile("cp.async.cg.shared.global [%0], [%1], 16;" :: "r"(daddr), "l"(g));
}

// ---------------- K1: supports = softmax(relu(E E^T)) -> bf16 hi/lo --------
__global__ void supports_kernel(const float* __restrict__ E) {
    int n = blockIdx.x;
    int t = threadIdx.x;                      // 256 threads, 8 cols each
    float e[10];
#pragma unroll
    for (int c = 0; c < 10; c++) e[c] = E[n * 10 + c];

    float vals[8];
    float vmax = 0.0f;
#pragma unroll
    for (int j = 0; j < 8; j++) {
        int m = j * 256 + t;
        float s = 0.0f;
#pragma unroll
        for (int c = 0; c < 10; c++) s = fmaf(e[c], E[m * 10 + c], s);
        s = fmaxf(s, 0.0f);
        vals[j] = s;
        vmax = fmaxf(vmax, s);
    }
    __shared__ float red[256];
    red[t] = vmax; __syncthreads();
    for (int s = 128; s > 0; s >>= 1) {
        if (t < s) red[t] = fmaxf(red[t], red[t + s]);
        __syncthreads();
    }
    vmax = red[0]; __syncthreads();

    float lsum = 0.0f;
#pragma unroll
    for (int j = 0; j < 8; j++) { vals[j] = expf(vals[j] - vmax); lsum += vals[j]; }
    red[t] = lsum; __syncthreads();
    for (int s = 128; s > 0; s >>= 1) {
        if (t < s) red[t] += red[t + s];
        __syncthreads();
    }
    float inv = 1.0f / red[0];
#pragma unroll
    for (int j = 0; j < 8; j++) {
        float v = vals[j] * inv;
        __nv_bfloat16 hi, lo;
        split_bf16(v, hi, lo);
        g_Ahi[(size_t)n * N_NODES + j * 256 + t] = hi;
        g_Alo[(size_t)n * N_NODES + j * 256 + t] = lo;
    }
}

// ---------------- K2: pack X0 (fp32 [node][bc]) + X0T hi/lo ([bc][node]) ---
__global__ void pack_kernel(const float* __restrict__ x, const float* __restrict__ st) {
    int n = blockIdx.x;
    for (int i = threadIdx.x; i < BC; i += blockDim.x) {
        int b = i / C_IN, c = i - b * C_IN;
        float v = (c < 2) ? x[(b * N_NODES + n) * 2 + c]
                          : st[(b * N_NODES + n) * 64 + (c - 2)];
        g_X0[n * BC + i] = v;
        __nv_bfloat16 hi, lo;
        split_bf16(v, hi, lo);
        g_X0Thi[(size_t)i * N_NODES + n] = hi;
        g_X0Tlo[(size_t)i * N_NODES + n] = lo;
    }
}

// ---------------- K2b: zero pad rows [BC..NPAD) of transposed arrays -------
__global__ void pad_kernel() {
    int idx = blockIdx.x * 256 + threadIdx.x;   // (NPAD-BC)*2048 = 131072
    if (idx < (NPAD - BC) * N_NODES) {
        size_t off = (size_t)BC * N_NODES + idx;
        g_X0Thi[off] = __float2bfloat16(0.f);
        g_X0Tlo[off] = __float2bfloat16(0.f);
        g_C0Thi[off] = __float2bfloat16(0.f);
        g_C0Tlo[off] = __float2bfloat16(0.f);
    }
}

// ---------------- HMMA GEMM: D[m,n] = sum_k A[m,k] * BT[n,k] ---------------
// bf16 3-split (AhiBhi + AhiBlo + AloBhi), fp32 acc.
// CTA tile 128x128, BK=32, 8 warps of 64x32. cp.async double buffer.
// smem per-buffer layout (49152B): Ahi@0, Alo@12288, Bhi@24576, Blo@36864.
// Each matrix tile: 2 k16-slices x 128 rows x 48B (16 bf16 padded-stride rows).
template <int MODE>
__global__ void __launch_bounds__(256, 1)
mma_gemm(const __nv_bfloat16* __restrict__ Ahi, const __nv_bfloat16* __restrict__ Alo,
         const __nv_bfloat16* __restrict__ Bhi, const __nv_bfloat16* __restrict__ Blo,
         float* __restrict__ Cf, __nv_bfloat16* __restrict__ CThi,
         __nv_bfloat16* __restrict__ CTlo, const float* __restrict__ Aux) {
    extern __shared__ char smem[];
    const uint32_t sb = smem_to_u32(smem);
    const int tid = threadIdx.x, wid = tid >> 5, lane = tid & 31;
    const int wr = wid >> 2, wc = wid & 3;            // warp tile: 64x32
    const int m0 = blockIdx.y * 128, n0 = blockIdx.x * 128;

    const __nv_bfloat16* srcs[4] = {
        Ahi + (size_t)m0 * N_NODES, Alo + (size_t)m0 * N_NODES,
        Bhi + (size_t)n0 * N_NODES, Blo + (size_t)n0 * N_NODES };

    float acc[4][4][4];
#pragma unroll
    for (int i = 0; i < 4; i++)
#pragma unroll
        for (int j = 0; j < 4; j++)
#pragma unroll
            for (int k = 0; k < 4; k++) acc[i][j][k] = 0.f;

    // per-thread copy decomposition: 2 units per matrix, 16B each
    const int c_row   = tid >> 2;            // 0..63 (+64 for second unit)
    const int c_q     = tid & 3;
    const int c_slice = c_q >> 1;
    const int c_half  = c_q & 1;

#define COPY_CHUNK(k0, bufi) do {                                             \
        _Pragma("unroll")                                                     \
        for (int _t = 0; _t < 4; _t++) {                                      \
            _Pragma("unroll")                                                 \
            for (int _i = 0; _i < 2; _i++) {                                  \
                int _row = c_row + _i * 64;                                   \
                uint32_t _d = sb + (bufi) * 49152 + _t * 12288 +              \
                              c_slice * 6144 + _row * 48 + c_half * 16;       \
                const void* _g = srcs[_t] + (size_t)_row * N_NODES + (k0)     \
                                 + c_slice * 16 + c_half * 8;                 \
                cp16(_d, _g);                                                 \
            }                                                                 \
        }                                                                     \
        asm volatile("cp.async.commit_group;");                               \
    } while (0)

    COPY_CHUNK(0, 0);

    const int NCHUNK = N_NODES / 32;   // 64
    for (int c = 0; c < NCHUNK; c++) {
        int buf = c & 1;
        if (c + 1 < NCHUNK) {
            COPY_CHUNK((c + 1) * 32, buf ^ 1);
            asm volatile("cp.async.wait_group 1;");
        } else {
            asm volatile("cp.async.wait_group 0;");
        }
        __syncthreads();

        uint32_t bA_hi = sb + buf * 49152;
        uint32_t bA_lo = bA_hi + 12288;
        uint32_t bB_hi = bA_hi + 24576;
        uint32_t bB_lo = bA_hi + 36864;

#pragma unroll
        for (int s = 0; s < 2; s++) {
            uint32_t a_hi[4][4], a_lo[4][4], b_hi[2][4], b_lo[2][4];
            // A frags: lane -> row (l&15), 16B col (l>>4)
            int a_roff = (wr * 64 + (lane & 15)) * 48 + (lane >> 4) * 16 + s * 6144;
#pragma unroll
            for (int mt = 0; mt < 4; mt++) {
                ldsm4(a_hi[mt], bA_hi + a_roff + mt * 16 * 48);
                ldsm4(a_lo[mt], bA_lo + a_roff + mt * 16 * 48);
            }
            // B frags: quad q = lane>>3: row_add=(q>>1)*8+(l&7), col16=(q&1)
            int q = lane >> 3, rl = lane & 7;
            int b_roff = (wc * 32 + (q >> 1) * 8 + rl) * 48 + (q & 1) * 16 + s * 6144;
#pragma unroll
            for (int p = 0; p < 2; p++) {
                ldsm4(b_hi[p], bB_hi + b_roff + p * 16 * 48);
                ldsm4(b_lo[p], bB_lo + b_roff + p * 16 * 48);
            }
#pragma unroll
            for (int mt = 0; mt < 4; mt++) {
#pragma unroll
                for (int nt = 0; nt < 4; nt++) {
                    const uint32_t* bh = &b_hi[nt >> 1][(nt & 1) * 2];
                    const uint32_t* bl = &b_lo[nt >> 1][(nt & 1) * 2];
                    mma_bf16(acc[mt][nt], a_hi[mt], bh);
                    mma_bf16(acc[mt][nt], a_hi[mt], bl);
                    mma_bf16(acc[mt][nt], a_lo[mt], bh);
                }
            }
        }
        __syncthreads();
    }
#undef COPY_CHUNK

    // ---- epilogue: fp32 row-major direct from fragments ----
    const int frow = lane >> 2, fcol = (lane & 3) * 2;
#pragma unroll
    for (int mt = 0; mt < 4; mt++) {
#pragma unroll
        for (int nt = 0; nt < 4; nt++) {
            int m = m0 + wr * 64 + mt * 16 + frow;
            int n = n0 + wc * 32 + nt * 8 + fcol;
            if (n < BC) {
                float* d0 = Cf + (size_t)m * BC + n;
                float* d1 = Cf + (size_t)(m + 8) * BC + n;
                if (MODE == 1) {
                    float2 x0 = *(const float2*)(Aux + (size_t)m * BC + n);
                    float2 x1 = *(const float2*)(Aux + (size_t)(m + 8) * BC + n);
                    float2 v0 = make_float2(2.f * acc[mt][nt][0] - x0.x,
                                            2.f * acc[mt][nt][1] - x0.y);
                    float2 v1 = make_float2(2.f * acc[mt][nt][2] - x1.x,
                                            2.f * acc[mt][nt][3] - x1.y);
                    *(float2*)d0 = v0;
                    *(float2*)d1 = v1;
                } else {
                    *(float2*)d0 = make_float2(acc[mt][nt][0], acc[mt][nt][1]);
                    *(float2*)d1 = make_float2(acc[mt][nt][2], acc[mt][nt][3]);
                }
            }
        }
    }

    if (MODE == 0) {
        // ---- transpose via smem -> bf16 hi/lo [n][node] ----
        float* Ct = (float*)smem;          // [128][132] fp32 = 67584B
        __syncthreads();
#pragma unroll
        for (int mt = 0; mt < 4; mt++) {
#pragma unroll
            for (int nt = 0; nt < 4; nt++) {
                int mloc = wr * 64 + mt * 16 + frow;
                int nloc = wc * 32 + nt * 8 + fcol;
                Ct[(nloc + 0) * 132 + mloc]     = acc[mt][nt][0];
                Ct[(nloc + 1) * 132 + mloc]     = acc[mt][nt][1];
                Ct[(nloc + 0) * 132 + mloc + 8] = acc[mt][nt][2];
                Ct[(nloc + 1) * 132 + mloc + 8] = acc[mt][nt][3];
            }
        }
        __syncthreads();
        // warp w handles n-row (it*8 + w); lane covers 4 m each
        for (int it = 0; it < 16; it++) {
            int nloc = it * 8 + wid;
            float4 v = *(float4*)&Ct[nloc * 132 + lane * 4];
            __nv_bfloat16 hi[4], lo[4];
            split_bf16(v.x, hi[0], lo[0]);
            split_bf16(v.y, hi[1], lo[1]);
            split_bf16(v.z, hi[2], lo[2]);
            split_bf16(v.w, hi[3], lo[3]);
            size_t off = (size_t)(n0 + nloc) * N_NODES + m0 + lane * 4;
            *(uint2*)(CThi + off) = *(uint2*)hi;
            *(uint2*)(CTlo + off) = *(uint2*)lo;
        }
    }
}

// ---------------- K4: gate projection + sigmoid + candidate pack -----------
__global__ void __launch_bounds__(128)
gate_kernel(const float* __restrict__ x, const float* __restrict__ st,
            const float* __restrict__ Wg, const float* __restrict__ bg) {
    __shared__ float in_s[16][IN3];
    int row0 = blockIdx.x * 16;
    int t = threadIdx.x;

    for (int idx = t; idx < 16 * IN3; idx += 128) {
        int rr = idx / IN3, i = idx - rr * IN3;
        int row = row0 + rr;
        int b = row >> 11, n = row & 2047;
        int k = i / C_IN, c = i - k * C_IN;
        const float* src = (k == 0) ? g_X0 : (k == 1) ? g_X1 : g_X2;
        in_s[rr][i] = src[n * BC + b * C_IN + c];
    }
    __syncthreads();

    int o = t;
    float acc[16];
#pragma unroll
    for (int rr = 0; rr < 16; rr++) acc[rr] = 0.0f;
    for (int i = 0; i < IN3; i++) {
        float w = Wg[i * GATE_OUT + o];
#pragma unroll
        for (int rr = 0; rr < 16; rr++) acc[rr] = fmaf(in_s[rr][i], w, acc[rr]);
    }
    float bias = bg[o];
#pragma unroll
    for (int rr = 0; rr < 16; rr++) {
        int row = row0 + rr;
        int b = row >> 11, n = row & 2047;
        float v = 1.0f / (1.0f + expf(-(acc[rr] + bias)));
        if (o < 64) {
            float sv = st[row * 64 + o];
            float cv = v * sv;                                  // z * state
            g_C0[n * BC + b * C_IN + 2 + o] = cv;
            __nv_bfloat16 hi, lo;
            split_bf16(cv, hi, lo);
            g_C0Thi[(size_t)(b * C_IN + 2 + o) * N_NODES + n] = hi;
            g_C0Tlo[(size_t)(b * C_IN + 2 + o) * N_NODES + n] = lo;
            if (o < 2) {
                float xv = x[row * 2 + o];
                g_C0[n * BC + b * C_IN + o] = xv;
                split_bf16(xv, hi, lo);
                g_C0Thi[(size_t)(b * C_IN + o) * N_NODES + n] = hi;
                g_C0Tlo[(size_t)(b * C_IN + o) * N_NODES + n] = lo;
            }
        } else {
            g_r[row * 64 + (o - 64)] = v;                        // r gate
        }
    }
}

// ---------------- K5: update projection + tanh + GRU blend -----------------
__global__ void __launch_bounds__(128)
update_kernel(const float* __restrict__ st, const float* __restrict__ Wu,
              const float* __restrict__ bu, float* __restrict__ out) {
    __shared__ float in_s[16][IN3];
    int row0 = blockIdx.x * 16;
    int t = threadIdx.x;

    for (int idx = t; idx < 16 * IN3; idx += 128) {
        int rr = idx / IN3, i = idx - rr * IN3;
        int row = row0 + rr;
        int b = row >> 11, n = row & 2047;
        int k = i / C_IN, c = i - k * C_IN;
        const float* src = (k == 0) ? g_C0 : (k == 1) ? g_C1 : g_C2;
        in_s[rr][i] = src[n * BC + b * C_IN + c];
    }
    __syncthreads();

    int o = t & 63, hh = t >> 6;
    float acc[8];
#pragma unroll
    for (int rr = 0; rr < 8; rr++) acc[rr] = 0.0f;
    for (int i = 0; i < IN3; i++) {
        float w = Wu[i * UPD_OUT + o];
#pragma unroll
        for (int rr = 0; rr < 8; rr++) acc[rr] = fmaf(in_s[hh * 8 + rr][i], w, acc[rr]);
    }
    float bias = bu[o];
#pragma unroll
    for (int rr = 0; rr < 8; rr++) {
        int row = row0 + hh * 8 + rr;
        float hc = tanhf(acc[rr] + bias);
        float rv = g_r[row * 64 + o];
        float sv = st[row * 64 + o];
        out[row * 64 + o] = rv * sv + (1.0f - rv) * hc;
    }
}

// ---------------- launch ----------------------------------------------------
extern "C" void kernel_launch(void* const* d_in, const int* in_sizes, int n_in,
                              void* d_out, int out_size) {
    const float* x  = (const float*)d_in[0];
    const float* st = (const float*)d_in[1];
    const float* E  = (const float*)d_in[2];
    const float* Wg = (const float*)d_in[3];
    const float* bg = (const float*)d_in[4];
    const float* Wu = (const float*)d_in[5];
    const float* bu = (const float*)d_in[6];
    float* out = (float*)d_out;

    __nv_bfloat16 *pAhi, *pAlo, *pX0Thi, *pX0Tlo, *pX1Thi, *pX1Tlo;
    __nv_bfloat16 *pC0Thi, *pC0Tlo, *pC1Thi, *pC1Tlo;
    float *pX0, *pX1, *pX2, *pC0, *pC1, *pC2;
    cudaGetSymbolAddress((void**)&pAhi,   g_Ahi);
    cudaGetSymbolAddress((void**)&pAlo,   g_Alo);
    cudaGetSymbolAddress((void**)&pX0Thi, g_X0Thi);
    cudaGetSymbolAddress((void**)&pX0Tlo, g_X0Tlo);
    cudaGetSymbolAddress((void**)&pX1Thi, g_X1Thi);
    cudaGetSymbolAddress((void**)&pX1Tlo, g_X1Tlo);
    cudaGetSymbolAddress((void**)&pC0Thi, g_C0Thi);
    cudaGetSymbolAddress((void**)&pC0Tlo, g_C0Tlo);
    cudaGetSymbolAddress((void**)&pC1Thi, g_C1Thi);
    cudaGetSymbolAddress((void**)&pC1Tlo, g_C1Tlo);
    cudaGetSymbolAddress((void**)&pX0, g_X0);
    cudaGetSymbolAddress((void**)&pX1, g_X1);
    cudaGetSymbolAddress((void**)&pX2, g_X2);
    cudaGetSymbolAddress((void**)&pC0, g_C0);
    cudaGetSymbolAddress((void**)&pC1, g_C1);
    cudaGetSymbolAddress((void**)&pC2, g_C2);

    const int SMEM_BYTES = 2 * 49152;   // 96KB (epilogue reuses 67.6KB)
    cudaFuncSetAttribute(mma_gemm<0>, cudaFuncAttributeMaxDynamicSharedMemorySize, SMEM_BYTES);
    cudaFuncSetAttribute(mma_gemm<1>, cudaFuncAttributeMaxDynamicSharedMemorySize, SMEM_BYTES);

    dim3 gg(NPAD / 128, N_NODES / 128);   // (17, 16)

    supports_kernel<<<N_NODES, 256>>>(E);
    pack_kernel<<<N_NODES, 256>>>(x, st);
    pad_kernel<<<512, 256>>>();

    // gate gconv: X1 = A X0 ; X2 = 2 A X1 - X0
    mma_gemm<0><<<gg, 256, SMEM_BYTES>>>(pAhi, pAlo, pX0Thi, pX0Tlo,
                                         pX1, pX1Thi, pX1Tlo, nullptr);
    mma_gemm<1><<<gg, 256, SMEM_BYTES>>>(pAhi, pAlo, pX1Thi, pX1Tlo,
                                         pX2, nullptr, nullptr, pX0);

    gate_kernel<<<(BATCH * N_NODES) / 16, 128>>>(x, st, Wg, bg);

    // update gconv: C1 = A C0 ; C2 = 2 A C1 - C0
    mma_gemm<0><<<gg, 256, SMEM_BYTES>>>(pAhi, pAlo, pC0Thi, pC0Tlo,
                                         pC1, pC1Thi, pC1Tlo, nullptr);
    mma_gemm<1><<<gg, 256, SMEM_BYTES>>>(pAhi, pAlo, pC1Thi, pC1Tlo,
                                         pC2, nullptr, nullptr, pC0);

    update_kernel<<<(BATCH * N_NODES) / 16, 128>>>(st, Wu, bu, out);
}

// round 6
// speedup vs baseline: 1.8757x; 1.0890x over previous
#include <cuda_runtime.h>
#include <cuda_bf16.h>
#include <math.h>
#include <stdint.h>

#define N_NODES 2048
#define BATCH   32
#define HIDDEN  64
#define C_IN    66                 // DIM_IN + HIDDEN
#define BC      2112               // BATCH * C_IN
#define NPAD    2176               // BC padded to multiple of 128
#define IN3     198                // 3 * C_IN
#define GATE_OUT 128
#define UPD_OUT  64

// ---------------- device scratch (static: no allocations allowed) ----------
__device__ __nv_bfloat16 g_Ahi[N_NODES * N_NODES];
__device__ __nv_bfloat16 g_Alo[N_NODES * N_NODES];
__device__ __nv_bfloat16 g_X0Thi[NPAD * N_NODES];
__device__ __nv_bfloat16 g_X0Tlo[NPAD * N_NODES];
__device__ __nv_bfloat16 g_X1Thi[NPAD * N_NODES];
__device__ __nv_bfloat16 g_X1Tlo[NPAD * N_NODES];
__device__ __nv_bfloat16 g_C0Thi[NPAD * N_NODES];
__device__ __nv_bfloat16 g_C0Tlo[NPAD * N_NODES];
__device__ __nv_bfloat16 g_C1Thi[NPAD * N_NODES];
__device__ __nv_bfloat16 g_C1Tlo[NPAD * N_NODES];
__device__ float g_X0[N_NODES * BC];
__device__ float g_X1[N_NODES * BC];
__device__ float g_X2[N_NODES * BC];
__device__ float g_C0[N_NODES * BC];
__device__ float g_C1[N_NODES * BC];
__device__ float g_C2[N_NODES * BC];
__device__ float g_r [BATCH * N_NODES * HIDDEN];

__device__ __forceinline__ uint32_t smem_to_u32(const void* p) {
    uint32_t a;
    asm("{ .reg .u64 t; cvta.to.shared.u64 t, %1; cvt.u32.u64 %0, t; }" : "=r"(a) : "l"(p));
    return a;
}
__device__ __forceinline__ void split_bf16(float v, __nv_bfloat16& hi, __nv_bfloat16& lo) {
    hi = __float2bfloat16(v);
    lo = __float2bfloat16(v - __bfloat162float(hi));
}
__device__ __forceinline__ void mma_bf16(float* c, const uint32_t* a, const uint32_t* b) {
    asm volatile(
        "mma.sync.aligned.m16n8k16.row.col.f32.bf16.bf16.f32 "
        "{%0,%1,%2,%3}, {%4,%5,%6,%7}, {%8,%9}, {%0,%1,%2,%3};"
        : "+f"(c[0]), "+f"(c[1]), "+f"(c[2]), "+f"(c[3])
        : "r"(a[0]), "r"(a[1]), "r"(a[2]), "r"(a[3]), "r"(b[0]), "r"(b[1]));
}
__device__ __forceinline__ void ldsm4(uint32_t* r, uint32_t addr) {
    asm volatile("ldmatrix.sync.aligned.m8n8.x4.shared.b16 {%0,%1,%2,%3}, [%4];"
                 : "=r"(r[0]), "=r"(r[1]), "=r"(r[2]), "=r"(r[3]) : "r"(addr));
}
__device__ __forceinline__ void cp16(uint32_t daddr, const void* g) {
    asm volatile("cp.async.cg.shared.global [%0], [%1], 16;" :: "r"(daddr), "l"(g));
}

// ---------------- K1: supports = softmax(relu(E E^T)) -> bf16 hi/lo --------
__global__ void supports_kernel(const float* __restrict__ E) {
    int n = blockIdx.x;
    int t = threadIdx.x;                      // 256 threads, 8 cols each
    float e[10];
#pragma unroll
    for (int c = 0; c < 10; c++) e[c] = E[n * 10 + c];

    float vals[8];
    float vmax = 0.0f;
#pragma unroll
    for (int j = 0; j < 8; j++) {
        int m = j * 256 + t;
        float s = 0.0f;
#pragma unroll
        for (int c = 0; c < 10; c++) s = fmaf(e[c], E[m * 10 + c], s);
        s = fmaxf(s, 0.0f);
        vals[j] = s;
        vmax = fmaxf(vmax, s);
    }
    __shared__ float red[256];
    red[t] = vmax; __syncthreads();
    for (int s = 128; s > 0; s >>= 1) {
        if (t < s) red[t] = fmaxf(red[t], red[t + s]);
        __syncthreads();
    }
    vmax = red[0]; __syncthreads();

    float lsum = 0.0f;
#pragma unroll
    for (int j = 0; j < 8; j++) { vals[j] = expf(vals[j] - vmax); lsum += vals[j]; }
    red[t] = lsum; __syncthreads();
    for (int s = 128; s > 0; s >>= 1) {
        if (t < s) red[t] += red[t + s];
        __syncthreads();
    }
    float inv = 1.0f / red[0];
#pragma unroll
    for (int j = 0; j < 8; j++) {
        float v = vals[j] * inv;
        __nv_bfloat16 hi, lo;
        split_bf16(v, hi, lo);
        g_Ahi[(size_t)n * N_NODES + j * 256 + t] = hi;
        g_Alo[(size_t)n * N_NODES + j * 256 + t] = lo;
    }
}

// ---------------- K2: pack X0 (fp32 [node][bc]) + X0T hi/lo ([bc][node]) ---
__global__ void pack_kernel(const float* __restrict__ x, const float* __restrict__ st) {
    int n = blockIdx.x;
    for (int i = threadIdx.x; i < BC; i += blockDim.x) {
        int b = i / C_IN, c = i - b * C_IN;
        float v = (c < 2) ? x[(b * N_NODES + n) * 2 + c]
                          : st[(b * N_NODES + n) * 64 + (c - 2)];
        g_X0[n * BC + i] = v;
        __nv_bfloat16 hi, lo;
        split_bf16(v, hi, lo);
        g_X0Thi[(size_t)i * N_NODES + n] = hi;
        g_X0Tlo[(size_t)i * N_NODES + n] = lo;
    }
}

// ---------------- K2b: zero pad rows [BC..NPAD) of transposed arrays -------
__global__ void pad_kernel() {
    int idx = blockIdx.x * 256 + threadIdx.x;   // (NPAD-BC)*2048 = 131072
    if (idx < (NPAD - BC) * N_NODES) {
        size_t off = (size_t)BC * N_NODES + idx;
        g_X0Thi[off] = __float2bfloat16(0.f);
        g_X0Tlo[off] = __float2bfloat16(0.f);
        g_C0Thi[off] = __float2bfloat16(0.f);
        g_C0Tlo[off] = __float2bfloat16(0.f);
    }
}

// ---------------- HMMA GEMM: D[m,n] = sum_k A[m,k] * BT[n,k] ---------------
// bf16 3-split (AhiBhi + AhiBlo + AloBhi), fp32 acc.
// CTA tile 256x128, 8 warps of 64x64, BK=32, cp.async double buffer.
// smem per buffer (73728B): Ahi@0 (2 slices x 12288), Alo@24576,
//                           Bhi@49152 (2 x 6144), Blo@61440.
// Row stride 48B (16 bf16 data + 16B pad) -> conflict-free ldmatrix.
template <int MODE>
__global__ void __launch_bounds__(256, 1)
mma_gemm(const __nv_bfloat16* __restrict__ Ahi, const __nv_bfloat16* __restrict__ Alo,
         const __nv_bfloat16* __restrict__ Bhi, const __nv_bfloat16* __restrict__ Blo,
         float* __restrict__ Cf, __nv_bfloat16* __restrict__ CThi,
         __nv_bfloat16* __restrict__ CTlo, const float* __restrict__ Aux) {
    extern __shared__ char smem[];
    const uint32_t sb = smem_to_u32(smem);
    const int tid = threadIdx.x, wid = tid >> 5, lane = tid & 31;
    const int wr = wid >> 1, wc = wid & 1;            // warp tile: 64x64
    const int m0 = blockIdx.y * 256, n0 = blockIdx.x * 128;

    const __nv_bfloat16* srcA[2] = { Ahi + (size_t)m0 * N_NODES,
                                     Alo + (size_t)m0 * N_NODES };
    const __nv_bfloat16* srcB[2] = { Bhi + (size_t)n0 * N_NODES,
                                     Blo + (size_t)n0 * N_NODES };

    float acc[4][8][4];
#pragma unroll
    for (int i = 0; i < 4; i++)
#pragma unroll
        for (int j = 0; j < 8; j++)
#pragma unroll
            for (int k = 0; k < 4; k++) acc[i][j][k] = 0.f;

#define COPY_CHUNK(k0, bufi) do {                                             \
        uint32_t _b = sb + (bufi) * 73728;                                    \
        _Pragma("unroll")                                                     \
        for (int _t = 0; _t < 2; _t++) {          /* A hi/lo: 4 units */      \
            _Pragma("unroll")                                                 \
            for (int _u = 0; _u < 4; _u++) {                                  \
                int _unit = _u * 256 + tid;                                   \
                int _row = _unit >> 2, _q = _unit & 3;                        \
                int _sl = _q >> 1, _hf = _q & 1;                              \
                cp16(_b + _t * 24576 + _sl * 12288 + _row * 48 + _hf * 16,    \
                     srcA[_t] + (size_t)_row * N_NODES + (k0) + _sl * 16 + _hf * 8); \
            }                                                                 \
        }                                                                     \
        _Pragma("unroll")                                                     \
        for (int _t = 0; _t < 2; _t++) {          /* B hi/lo: 2 units */      \
            _Pragma("unroll")                                                 \
            for (int _u = 0; _u < 2; _u++) {                                  \
                int _unit = _u * 256 + tid;                                   \
                int _row = _unit >> 2, _q = _unit & 3;                        \
                int _sl = _q >> 1, _hf = _q & 1;                              \
                cp16(_b + 49152 + _t * 12288 + _sl * 6144 + _row * 48 + _hf * 16, \
                     srcB[_t] + (size_t)_row * N_NODES + (k0) + _sl * 16 + _hf * 8); \
            }                                                                 \
        }                                                                     \
        asm volatile("cp.async.commit_group;");                               \
    } while (0)

    COPY_CHUNK(0, 0);

    const int NCHUNK = N_NODES / 32;   // 64
    for (int c = 0; c < NCHUNK; c++) {
        int buf = c & 1;
        if (c + 1 < NCHUNK) {
            COPY_CHUNK((c + 1) * 32, buf ^ 1);
            asm volatile("cp.async.wait_group 1;");
        } else {
            asm volatile("cp.async.wait_group 0;");
        }
        __syncthreads();

        uint32_t base = sb + buf * 73728;

#pragma unroll
        for (int s = 0; s < 2; s++) {
            uint32_t a_hi[4][4], a_lo[4][4], b_hi[4][4], b_lo[4][4];
            int a_roff = (wr * 64 + (lane & 15)) * 48 + (lane >> 4) * 16 + s * 12288;
#pragma unroll
            for (int mt = 0; mt < 4; mt++) {
                ldsm4(a_hi[mt], base + a_roff + mt * 768);
                ldsm4(a_lo[mt], base + 24576 + a_roff + mt * 768);
            }
            int q = lane >> 3, rl = lane & 7;
            int b_roff = (wc * 64 + (q >> 1) * 8 + rl) * 48 + (q & 1) * 16 + s * 6144;
#pragma unroll
            for (int p = 0; p < 4; p++) {
                ldsm4(b_hi[p], base + 49152 + b_roff + p * 768);
                ldsm4(b_lo[p], base + 61440 + b_roff + p * 768);
            }
#pragma unroll
            for (int mt = 0; mt < 4; mt++) {
#pragma unroll
                for (int nt = 0; nt < 8; nt++) {
                    const uint32_t* bh = &b_hi[nt >> 1][(nt & 1) * 2];
                    const uint32_t* bl = &b_lo[nt >> 1][(nt & 1) * 2];
                    mma_bf16(acc[mt][nt], a_hi[mt], bh);
                    mma_bf16(acc[mt][nt], a_hi[mt], bl);
                    mma_bf16(acc[mt][nt], a_lo[mt], bh);
                }
            }
        }
        __syncthreads();
    }
#undef COPY_CHUNK

    // ---- epilogue: fp32 row-major direct from fragments ----
    const int frow = lane >> 2, fcol = (lane & 3) * 2;
#pragma unroll
    for (int mt = 0; mt < 4; mt++) {
#pragma unroll
        for (int nt = 0; nt < 8; nt++) {
            int m = m0 + wr * 64 + mt * 16 + frow;
            int n = n0 + wc * 64 + nt * 8 + fcol;
            if (n < BC) {
                float* d0 = Cf + (size_t)m * BC + n;
                float* d1 = Cf + (size_t)(m + 8) * BC + n;
                if (MODE == 1) {
                    float2 x0 = *(const float2*)(Aux + (size_t)m * BC + n);
                    float2 x1 = *(const float2*)(Aux + (size_t)(m + 8) * BC + n);
                    *(float2*)d0 = make_float2(2.f * acc[mt][nt][0] - x0.x,
                                               2.f * acc[mt][nt][1] - x0.y);
                    *(float2*)d1 = make_float2(2.f * acc[mt][nt][2] - x1.x,
                                               2.f * acc[mt][nt][3] - x1.y);
                } else {
                    *(float2*)d0 = make_float2(acc[mt][nt][0], acc[mt][nt][1]);
                    *(float2*)d1 = make_float2(acc[mt][nt][2], acc[mt][nt][3]);
                }
            }
        }
    }

    if (MODE == 0) {
        // ---- transpose via smem -> bf16 hi/lo [n][node] ----
        float* Ct = (float*)smem;          // [128][264] fp32 = 135168B
        __syncthreads();
#pragma unroll
        for (int mt = 0; mt < 4; mt++) {
#pragma unroll
            for (int nt = 0; nt < 8; nt++) {
                int mloc = wr * 64 + mt * 16 + frow;
                int nloc = wc * 64 + nt * 8 + fcol;
                Ct[(nloc + 0) * 264 + mloc]     = acc[mt][nt][0];
                Ct[(nloc + 1) * 264 + mloc]     = acc[mt][nt][1];
                Ct[(nloc + 0) * 264 + mloc + 8] = acc[mt][nt][2];
                Ct[(nloc + 1) * 264 + mloc + 8] = acc[mt][nt][3];
            }
        }
        __syncthreads();
        for (int it = 0; it < 16; it++) {
            int nloc = it * 8 + wid;
#pragma unroll
            for (int j = 0; j < 2; j++) {
                int mloc = lane * 4 + j * 128;
                float4 v = *(float4*)&Ct[nloc * 264 + mloc];
                __nv_bfloat16 hi[4], lo[4];
                split_bf16(v.x, hi[0], lo[0]);
                split_bf16(v.y, hi[1], lo[1]);
                split_bf16(v.z, hi[2], lo[2]);
                split_bf16(v.w, hi[3], lo[3]);
                size_t off = (size_t)(n0 + nloc) * N_NODES + m0 + mloc;
                *(uint2*)(CThi + off) = *(uint2*)hi;
                *(uint2*)(CTlo + off) = *(uint2*)lo;
            }
        }
    }
}

// ---------------- K4: gate projection + sigmoid + candidate pack -----------
__global__ void __launch_bounds__(128)
gate_kernel(const float* __restrict__ x, const float* __restrict__ st,
            const float* __restrict__ Wg, const float* __restrict__ bg) {
    __shared__ float in_s[16][IN3];
    int row0 = blockIdx.x * 16;
    int t = threadIdx.x;

    for (int idx = t; idx < 16 * IN3; idx += 128) {
        int rr = idx / IN3, i = idx - rr * IN3;
        int row = row0 + rr;
        int b = row >> 11, n = row & 2047;
        int k = i / C_IN, c = i - k * C_IN;
        const float* src = (k == 0) ? g_X0 : (k == 1) ? g_X1 : g_X2;
        in_s[rr][i] = src[n * BC + b * C_IN + c];
    }
    __syncthreads();

    int o = t;
    float acc[16];
#pragma unroll
    for (int rr = 0; rr < 16; rr++) acc[rr] = 0.0f;
    for (int i = 0; i < IN3; i++) {
        float w = Wg[i * GATE_OUT + o];
#pragma unroll
        for (int rr = 0; rr < 16; rr++) acc[rr] = fmaf(in_s[rr][i], w, acc[rr]);
    }
    float bias = bg[o];
#pragma unroll
    for (int rr = 0; rr < 16; rr++) {
        int row = row0 + rr;
        int b = row >> 11, n = row & 2047;
        float v = 1.0f / (1.0f + expf(-(acc[rr] + bias)));
        if (o < 64) {
            float sv = st[row * 64 + o];
            float cv = v * sv;                                  // z * state
            g_C0[n * BC + b * C_IN + 2 + o] = cv;
            __nv_bfloat16 hi, lo;
            split_bf16(cv, hi, lo);
            g_C0Thi[(size_t)(b * C_IN + 2 + o) * N_NODES + n] = hi;
            g_C0Tlo[(size_t)(b * C_IN + 2 + o) * N_NODES + n] = lo;
            if (o < 2) {
                float xv = x[row * 2 + o];
                g_C0[n * BC + b * C_IN + o] = xv;
                split_bf16(xv, hi, lo);
                g_C0Thi[(size_t)(b * C_IN + o) * N_NODES + n] = hi;
                g_C0Tlo[(size_t)(b * C_IN + o) * N_NODES + n] = lo;
            }
        } else {
            g_r[row * 64 + (o - 64)] = v;                        // r gate
        }
    }
}

// ---------------- K5: update projection + tanh + GRU blend -----------------
__global__ void __launch_bounds__(128)
update_kernel(const float* __restrict__ st, const float* __restrict__ Wu,
              const float* __restrict__ bu, float* __restrict__ out) {
    __shared__ float in_s[16][IN3];
    int row0 = blockIdx.x * 16;
    int t = threadIdx.x;

    for (int idx = t; idx < 16 * IN3; idx += 128) {
        int rr = idx / IN3, i = idx - rr * IN3;
        int row = row0 + rr;
        int b = row >> 11, n = row & 2047;
        int k = i / C_IN, c = i - k * C_IN;
        const float* src = (k == 0) ? g_C0 : (k == 1) ? g_C1 : g_C2;
        in_s[rr][i] = src[n * BC + b * C_IN + c];
    }
    __syncthreads();

    int o = t & 63, hh = t >> 6;
    float acc[8];
#pragma unroll
    for (int rr = 0; rr < 8; rr++) acc[rr] = 0.0f;
    for (int i = 0; i < IN3; i++) {
        float w = Wu[i * UPD_OUT + o];
#pragma unroll
        for (int rr = 0; rr < 8; rr++) acc[rr] = fmaf(in_s[hh * 8 + rr][i], w, acc[rr]);
    }
    float bias = bu[o];
#pragma unroll
    for (int rr = 0; rr < 8; rr++) {
        int row = row0 + hh * 8 + rr;
        float hc = tanhf(acc[rr] + bias);
        float rv = g_r[row * 64 + o];
        float sv = st[row * 64 + o];
        out[row * 64 + o] = rv * sv + (1.0f - rv) * hc;
    }
}

// ---------------- launch ----------------------------------------------------
extern "C" void kernel_launch(void* const* d_in, const int* in_sizes, int n_in,
                              void* d_out, int out_size) {
    const float* x  = (const float*)d_in[0];
    const float* st = (const float*)d_in[1];
    const float* E  = (const float*)d_in[2];
    const float* Wg = (const float*)d_in[3];
    const float* bg = (const float*)d_in[4];
    const float* Wu = (const float*)d_in[5];
    const float* bu = (const float*)d_in[6];
    float* out = (float*)d_out;

    __nv_bfloat16 *pAhi, *pAlo, *pX0Thi, *pX0Tlo, *pX1Thi, *pX1Tlo;
    __nv_bfloat16 *pC0Thi, *pC0Tlo, *pC1Thi, *pC1Tlo;
    float *pX0, *pX1, *pX2, *pC0, *pC1, *pC2;
    cudaGetSymbolAddress((void**)&pAhi,   g_Ahi);
    cudaGetSymbolAddress((void**)&pAlo,   g_Alo);
    cudaGetSymbolAddress((void**)&pX0Thi, g_X0Thi);
    cudaGetSymbolAddress((void**)&pX0Tlo, g_X0Tlo);
    cudaGetSymbolAddress((void**)&pX1Thi, g_X1Thi);
    cudaGetSymbolAddress((void**)&pX1Tlo, g_X1Tlo);
    cudaGetSymbolAddress((void**)&pC0Thi, g_C0Thi);
    cudaGetSymbolAddress((void**)&pC0Tlo, g_C0Tlo);
    cudaGetSymbolAddress((void**)&pC1Thi, g_C1Thi);
    cudaGetSymbolAddress((void**)&pC1Tlo, g_C1Tlo);
    cudaGetSymbolAddress((void**)&pX0, g_X0);
    cudaGetSymbolAddress((void**)&pX1, g_X1);
    cudaGetSymbolAddress((void**)&pX2, g_X2);
    cudaGetSymbolAddress((void**)&pC0, g_C0);
    cudaGetSymbolAddress((void**)&pC1, g_C1);
    cudaGetSymbolAddress((void**)&pC2, g_C2);

    const int SMEM_BYTES = 2 * 73728;   // 147456 (epilogue Ct uses 135168)
    cudaFuncSetAttribute(mma_gemm<0>, cudaFuncAttributeMaxDynamicSharedMemorySize, SMEM_BYTES);
    cudaFuncSetAttribute(mma_gemm<1>, cudaFuncAttributeMaxDynamicSharedMemorySize, SMEM_BYTES);

    dim3 gg(NPAD / 128, N_NODES / 256);   // (17, 8) = 136 CTAs, single wave

    supports_kernel<<<N_NODES, 256>>>(E);
    pack_kernel<<<N_NODES, 256>>>(x, st);
    pad_kernel<<<512, 256>>>();

    // gate gconv: X1 = A X0 ; X2 = 2 A X1 - X0
    mma_gemm<0><<<gg, 256, SMEM_BYTES>>>(pAhi, pAlo, pX0Thi, pX0Tlo,
                                         pX1, pX1Thi, pX1Tlo, nullptr);
    mma_gemm<1><<<gg, 256, SMEM_BYTES>>>(pAhi, pAlo, pX1Thi, pX1Tlo,
                                         pX2, nullptr, nullptr, pX0);

    gate_kernel<<<(BATCH * N_NODES) / 16, 128>>>(x, st, Wg, bg);

    // update gconv: C1 = A C0 ; C2 = 2 A C1 - C0
    mma_gemm<0><<<gg, 256, SMEM_BYTES>>>(pAhi, pAlo, pC0Thi, pC0Tlo,
                                         pC1, pC1Thi, pC1Tlo, nullptr);
    mma_gemm<1><<<gg, 256, SMEM_BYTES>>>(pAhi, pAlo, pC1Thi, pC1Tlo,
                                         pC2, nullptr, nullptr, pC0);

    update_kernel<<<(BATCH * N_NODES) / 16, 128>>>(st, Wu, bu, out);
}